// round 11
// baseline (speedup 1.0000x reference)
#include <cuda_runtime.h>
#include <math.h>

// ---------------------------------------------------------------------------
// HumanPoseModule. local_c = R_p^T R_c (root cancels; orthonormal).
// glb staged in smem (pure float4 memcpy; stride-60 is conflict-free for
// LDS.128). ori prefetched entirely into registers at kernel entry
// (12 back-to-back vector LDGs, MLP~12, overlapped with staging+barrier).
// Output-sequential joint order, float4 store buffering.
// ---------------------------------------------------------------------------

#define FDIV(a,b) __fdividef((a),(b))

constexpr int TPB = 256;
constexpr int SMEM_BYTES = TPB * 60 * 4;   // 61,440 B -> 3 blocks/SM

// Octant-reduced atan2 for y >= 0 (result in [0, pi]); deg-11 minimax, ~2e-8.
__device__ __forceinline__ float fast_atan2_pos(float y, float x) {
    float ax = fabsf(x);
    float mn = fminf(y, ax);
    float mx = fmaxf(y, ax);
    float t  = FDIV(mn, mx);
    float t2 = t * t;
    float p = -0.0117212f;
    p = fmaf(p, t2,  0.05265332f);
    p = fmaf(p, t2, -0.11643287f);
    p = fmaf(p, t2,  0.19354346f);
    p = fmaf(p, t2, -0.33262347f);
    p = fmaf(p, t2,  0.99997726f);
    p = p * t;
    float r = (y > ax) ? (1.57079632679f - p) : p;
    if (x < 0.0f) r = 3.14159265359f - r;
    return r;
}

__device__ __forceinline__ void r6d_core(float a1x, float a1y, float a1z,
                                         float a2x, float a2y, float a2z,
                                         float R[9]) {
    float in1 = rsqrtf(a1x*a1x + a1y*a1y + a1z*a1z);
    float b1x = a1x*in1, b1y = a1y*in1, b1z = a1z*in1;

    float dt = b1x*a2x + b1y*a2y + b1z*a2z;
    float b2x = a2x - dt*b1x, b2y = a2y - dt*b1y, b2z = a2z - dt*b1z;
    float in2 = rsqrtf(b2x*b2x + b2y*b2y + b2z*b2z);
    b2x *= in2; b2y *= in2; b2z *= in2;

    R[0]=b1x; R[1]=b1y; R[2]=b1z;
    R[3]=b2x; R[4]=b2y; R[5]=b2z;
    R[6] = b1y*b2z - b1z*b2y;
    R[7] = b1z*b2x - b1x*b2z;
    R[8] = b1x*b2y - b1y*b2x;
}

// From smem, vector loads. A16: 16B-aligned offset.
template <bool A16>
__device__ __forceinline__ void r6d_to_mat(const float* __restrict__ p, float R[9]) {
    float a1x, a1y, a1z, a2x, a2y, a2z;
    if (A16) {
        float4 v = *(const float4*)(p);
        float2 w = *(const float2*)(p + 4);
        a1x = v.x; a1y = v.y; a1z = v.z; a2x = v.w; a2y = w.x; a2z = w.y;
    } else {
        float2 v = *(const float2*)(p);
        float4 w = *(const float4*)(p + 2);
        a1x = v.x; a1y = v.y; a1z = w.x; a2x = w.y; a2y = w.z; a2z = w.w;
    }
    r6d_core(a1x, a1y, a1z, a2x, a2y, a2z, R);
}

// C = A^T @ B
__device__ __forceinline__ void mat_tmul(const float A[9], const float B[9], float C[9]) {
#pragma unroll
    for (int i = 0; i < 3; i++)
#pragma unroll
        for (int j = 0; j < 3; j++)
            C[3*i+j] = A[0+i]*B[0+j] + A[3+i]*B[3+j] + A[6+i]*B[6+j];
}

// matrix -> axis-angle (reference-equivalent; see prior-round derivations)
__device__ __forceinline__ void mat_to_aa(const float m[9],
                                          float& o0, float& o1, float& o2) {
    float m00=m[0], m01=m[1], m02=m[2];
    float m10=m[3], m11=m[4], m12=m[5];
    float m20=m[6], m21=m[7], m22=m[8];

    float w0 = fmaxf(1.0f + m00 + m11 + m22, 0.0f);
    float w1 = fmaxf(1.0f + m00 - m11 - m22, 0.0f);
    float w2 = fmaxf(1.0f - m00 + m11 - m22, 0.0f);
    float w3 = fmaxf(1.0f - m00 - m11 + m22, 0.0f);

    int idx = 0; float best = w0;
    if (w1 > best) { best = w1; idx = 1; }
    if (w2 > best) { best = w2; idx = 2; }
    if (w3 > best) { best = w3; idx = 3; }

    float d21 = m21 - m12, d02 = m02 - m20, d10 = m10 - m01;
    float s10 = m10 + m01, s02 = m02 + m20, s21 = m21 + m12;

    float c0, c1, c2, c3;
    if (idx == 0)      { c0 = w0;  c1 = d21; c2 = d02; c3 = d10; }
    else if (idx == 1) { c0 = d21; c1 = w1;  c2 = s10; c3 = s02; }
    else if (idx == 2) { c0 = d02; c1 = s10; c2 = w2;  c3 = s21; }
    else               { c0 = d10; c1 = s02; c2 = s21; c3 = w3;  }

    float id = 0.5f * rsqrtf(best);     // best >= 1 (traces sum to 4)
    float q0 = c0*id, q1 = c1*id, q2 = c2*id, q3 = c3*id;

    float nrm2 = fmaxf(q1*q1 + q2*q2 + q3*q3, 1e-30f);
    float nrm  = nrm2 * rsqrtf(nrm2);
    float half = fast_atan2_pos(nrm, q0);
    float ang  = 2.0f * half;

    float scale;
    if (fabsf(ang) < 1e-6f) {
        scale = FDIV(1.0f, 0.5f - ang*ang*(1.0f/48.0f));
    } else {
        float l2  = nrm2 + q0*q0;           // >= 0.25, never 0
        float len = l2 * rsqrtf(l2);
        scale = FDIV(ang * len, nrm);
    }
    o0 = q1*scale; o1 = q2*scale; o2 = q3*scale;
}

__global__ void __launch_bounds__(TPB, 3)
pose_kernel(const float* __restrict__ glb,   // (BT, 10, 6)
            const float* __restrict__ ori,   // (BT, 6, 6)
            float* __restrict__ out,         // (BT, 24, 3)
            int n)
{
    extern __shared__ float sg[];   // [TPB][60] unpadded

    int base = blockIdx.x * TPB;
    int samples = n - base; if (samples > TPB) samples = TPB;
    int t = threadIdx.x;

    // ---- prefetch ALL ori for this thread's sample into registers ----
    // 12 back-to-back vector LDGs -> high MLP, single latency exposure
    // overlapped with the staging memcpy + barrier below.
    float4 oA0; float2 oA1;   // O0 root     (op+0,  16B-aligned)
    float2 oB0; float4 oB1;   // O1 -> j4    (op+6,  8B-aligned)
    float4 oC0; float2 oC1;   // O2 -> j5    (op+12)
    float2 oD0; float4 oD1;   // O3 -> j15   (op+18)
    float4 oE0; float2 oE1;   // O4 -> j18   (op+24)
    float2 oF0; float4 oF1;   // O5 -> j19   (op+30)
    if (t < samples) {
        const float* op = ori + (size_t)(base + t) * 36;
        oA0 = *(const float4*)(op + 0);  oA1 = *(const float2*)(op + 4);
        oB0 = *(const float2*)(op + 6);  oB1 = *(const float4*)(op + 8);
        oC0 = *(const float4*)(op + 12); oC1 = *(const float2*)(op + 16);
        oD0 = *(const float2*)(op + 18); oD1 = *(const float4*)(op + 20);
        oE0 = *(const float4*)(op + 24); oE1 = *(const float2*)(op + 28);
        oF0 = *(const float2*)(op + 30); oF1 = *(const float4*)(op + 32);
    }

    // ---- stage glb: straight float4 memcpy (coalesced, no remap) ----
    {
        const float4* __restrict__ src = (const float4*)(glb + (size_t)base * 60);
        float4* dst = (float4*)sg;
        int nf4 = samples * 15;           // 60/4 per sample
#pragma unroll 4
        for (int j = t; j < nf4; j += TPB) dst[j] = src[j];
    }
    __syncthreads();
    if (t >= samples) return;

    const float* gp = sg + t * 60;
    float* po = out + (size_t)(base + t) * 72;

    float A[9], B[9], C[9], L[9], T[9];
    float a0,a1,a2, b0,b1,b2, c0,c1,c2, d0,d1,d2;

    // ---- group 1: joints 0..3 (children of root: local == own R) ----
    r6d_core(oA0.x,oA0.y,oA0.z, oA0.w,oA1.x,oA1.y, L); mat_to_aa(L, a0,a1,a2); // j0 = root
    r6d_to_mat<true >(gp + 0, A);  mat_to_aa(A, b0,b1,b2);   // j1 = R1 (keep)
    r6d_to_mat<false>(gp + 6, B);  mat_to_aa(B, c0,c1,c2);   // j2 = R2 (keep)
    r6d_to_mat<true >(gp + 12, C); mat_to_aa(C, d0,d1,d2);   // j3 = R3 (keep)
    *(float4*)(po + 0) = make_float4(a0,a1,a2,b0);
    *(float4*)(po + 4) = make_float4(b1,b2,c0,c1);
    *(float4*)(po + 8) = make_float4(c2,d0,d1,d2);

    // ---- group 2: joints 4..7 (7 ignored) ----
    r6d_core(oB0.x,oB0.y,oB1.x, oB1.y,oB1.z,oB1.w, T);
    mat_tmul(A, T, L); mat_to_aa(L, a0,a1,a2);               // j4 = R1^T O1
    r6d_core(oC0.x,oC0.y,oC0.z, oC0.w,oC1.x,oC1.y, T);
    mat_tmul(B, T, L); mat_to_aa(L, b0,b1,b2);               // j5 = R2^T O2
    float R6[9];
    r6d_to_mat<false>(gp + 18, R6); mat_tmul(C, R6, L); mat_to_aa(L, c0,c1,c2); // j6 = R3^T R6
    *(float4*)(po + 12) = make_float4(a0,a1,a2,b0);
    *(float4*)(po + 16) = make_float4(b1,b2,c0,c1);
    *(float4*)(po + 20) = make_float4(c2,0.f,0.f,0.f);

    // ---- group 3: joints 8..11 (8,10,11 ignored) ----
    float R9[9];
    r6d_to_mat<true >(gp + 24, R9); mat_tmul(R6, R9, L); mat_to_aa(L, b0,b1,b2); // j9
    *(float4*)(po + 24) = make_float4(0.f,0.f,0.f,b0);
    *(float4*)(po + 28) = make_float4(b1,b2,0.f,0.f);
    *(float4*)(po + 32) = make_float4(0.f,0.f,0.f,0.f);

    // ---- group 4: joints 12..15 ----
    r6d_to_mat<false>(gp + 30, A); mat_tmul(R9, A, L); mat_to_aa(L, a0,a1,a2); // j12 (A=R12)
    r6d_to_mat<true >(gp + 36, B); mat_tmul(R9, B, L); mat_to_aa(L, b0,b1,b2); // j13 (B=R13)
    r6d_to_mat<false>(gp + 42, C); mat_tmul(R9, C, L); mat_to_aa(L, c0,c1,c2); // j14 (C=R14)
    r6d_core(oD0.x,oD0.y,oD1.x, oD1.y,oD1.z,oD1.w, T);
    mat_tmul(A, T, L); mat_to_aa(L, d0,d1,d2);               // j15 = R12^T O3
    *(float4*)(po + 36) = make_float4(a0,a1,a2,b0);
    *(float4*)(po + 40) = make_float4(b1,b2,c0,c1);
    *(float4*)(po + 44) = make_float4(c2,d0,d1,d2);

    // ---- group 5: joints 16..19 ----
    r6d_to_mat<true >(gp + 48, A); mat_tmul(B, A, L); mat_to_aa(L, a0,a1,a2);  // j16 = R13^T R16
    r6d_to_mat<false>(gp + 54, B); mat_tmul(C, B, L); mat_to_aa(L, b0,b1,b2);  // j17 = R14^T R17
    r6d_core(oE0.x,oE0.y,oE0.z, oE0.w,oE1.x,oE1.y, T);
    mat_tmul(A, T, L); mat_to_aa(L, c0,c1,c2);               // j18 = R16^T O4
    r6d_core(oF0.x,oF0.y,oF1.x, oF1.y,oF1.z,oF1.w, T);
    mat_tmul(B, T, L); mat_to_aa(L, d0,d1,d2);               // j19 = R17^T O5
    *(float4*)(po + 48) = make_float4(a0,a1,a2,b0);
    *(float4*)(po + 52) = make_float4(b1,b2,c0,c1);
    *(float4*)(po + 56) = make_float4(c2,d0,d1,d2);

    // ---- group 6: joints 20..23 (all ignored) ----
    *(float4*)(po + 60) = make_float4(0.f,0.f,0.f,0.f);
    *(float4*)(po + 64) = make_float4(0.f,0.f,0.f,0.f);
    *(float4*)(po + 68) = make_float4(0.f,0.f,0.f,0.f);
}

extern "C" void kernel_launch(void* const* d_in, const int* in_sizes, int n_in,
                              void* d_out, int out_size) {
    const float* glb;
    const float* ori;
    if (in_sizes[0] >= in_sizes[1]) {
        glb = (const float*)d_in[0];
        ori = (const float*)d_in[1];
    } else {
        glb = (const float*)d_in[1];
        ori = (const float*)d_in[0];
    }
    int n = out_size / 72;

    static bool attr_set = false;
    if (!attr_set) {
        cudaFuncSetAttribute(pose_kernel,
                             cudaFuncAttributeMaxDynamicSharedMemorySize,
                             SMEM_BYTES);
        attr_set = true;
    }

    const int blocks = (n + TPB - 1) / TPB;
    pose_kernel<<<blocks, TPB, SMEM_BYTES>>>(glb, ori, (float*)d_out, n);
}

// round 12
// speedup vs baseline: 1.1310x; 1.1310x over previous
#include <cuda_runtime.h>
#include <math.h>

// ---------------------------------------------------------------------------
// HumanPoseModule. local_c = R_p^T R_c (root cancels; orthonormal).
// glb staged in smem (pure float4 memcpy; stride-60 conflict-free LDS.128).
// ori prefetched just-in-time, one joint-group ahead (short live ranges,
// ~12 extra live floats peak -> no spills, unlike all-at-entry prefetch).
// Output-sequential joint order, float4 store buffering.
// ---------------------------------------------------------------------------

#define FDIV(a,b) __fdividef((a),(b))

constexpr int TPB = 256;
constexpr int SMEM_BYTES = TPB * 60 * 4;   // 61,440 B -> 3 blocks/SM

// Octant-reduced atan2 for y >= 0 (result in [0, pi]); deg-11 minimax, ~2e-8.
__device__ __forceinline__ float fast_atan2_pos(float y, float x) {
    float ax = fabsf(x);
    float mn = fminf(y, ax);
    float mx = fmaxf(y, ax);
    float t  = FDIV(mn, mx);
    float t2 = t * t;
    float p = -0.0117212f;
    p = fmaf(p, t2,  0.05265332f);
    p = fmaf(p, t2, -0.11643287f);
    p = fmaf(p, t2,  0.19354346f);
    p = fmaf(p, t2, -0.33262347f);
    p = fmaf(p, t2,  0.99997726f);
    p = p * t;
    float r = (y > ax) ? (1.57079632679f - p) : p;
    if (x < 0.0f) r = 3.14159265359f - r;
    return r;
}

__device__ __forceinline__ void r6d_core(float a1x, float a1y, float a1z,
                                         float a2x, float a2y, float a2z,
                                         float R[9]) {
    float in1 = rsqrtf(a1x*a1x + a1y*a1y + a1z*a1z);
    float b1x = a1x*in1, b1y = a1y*in1, b1z = a1z*in1;

    float dt = b1x*a2x + b1y*a2y + b1z*a2z;
    float b2x = a2x - dt*b1x, b2y = a2y - dt*b1y, b2z = a2z - dt*b1z;
    float in2 = rsqrtf(b2x*b2x + b2y*b2y + b2z*b2z);
    b2x *= in2; b2y *= in2; b2z *= in2;

    R[0]=b1x; R[1]=b1y; R[2]=b1z;
    R[3]=b2x; R[4]=b2y; R[5]=b2z;
    R[6] = b1y*b2z - b1z*b2y;
    R[7] = b1z*b2x - b1x*b2z;
    R[8] = b1x*b2y - b1y*b2x;
}

// From smem, vector loads. A16: 16B-aligned offset.
template <bool A16>
__device__ __forceinline__ void r6d_to_mat(const float* __restrict__ p, float R[9]) {
    float a1x, a1y, a1z, a2x, a2y, a2z;
    if (A16) {
        float4 v = *(const float4*)(p);
        float2 w = *(const float2*)(p + 4);
        a1x = v.x; a1y = v.y; a1z = v.z; a2x = v.w; a2y = w.x; a2z = w.y;
    } else {
        float2 v = *(const float2*)(p);
        float4 w = *(const float4*)(p + 2);
        a1x = v.x; a1y = v.y; a1z = w.x; a2x = w.y; a2y = w.z; a2z = w.w;
    }
    r6d_core(a1x, a1y, a1z, a2x, a2y, a2z, R);
}

// C = A^T @ B
__device__ __forceinline__ void mat_tmul(const float A[9], const float B[9], float C[9]) {
#pragma unroll
    for (int i = 0; i < 3; i++)
#pragma unroll
        for (int j = 0; j < 3; j++)
            C[3*i+j] = A[0+i]*B[0+j] + A[3+i]*B[3+j] + A[6+i]*B[6+j];
}

// matrix -> axis-angle (reference-equivalent; see prior-round derivations)
__device__ __forceinline__ void mat_to_aa(const float m[9],
                                          float& o0, float& o1, float& o2) {
    float m00=m[0], m01=m[1], m02=m[2];
    float m10=m[3], m11=m[4], m12=m[5];
    float m20=m[6], m21=m[7], m22=m[8];

    float w0 = fmaxf(1.0f + m00 + m11 + m22, 0.0f);
    float w1 = fmaxf(1.0f + m00 - m11 - m22, 0.0f);
    float w2 = fmaxf(1.0f - m00 + m11 - m22, 0.0f);
    float w3 = fmaxf(1.0f - m00 - m11 + m22, 0.0f);

    int idx = 0; float best = w0;
    if (w1 > best) { best = w1; idx = 1; }
    if (w2 > best) { best = w2; idx = 2; }
    if (w3 > best) { best = w3; idx = 3; }

    float d21 = m21 - m12, d02 = m02 - m20, d10 = m10 - m01;
    float s10 = m10 + m01, s02 = m02 + m20, s21 = m21 + m12;

    float c0, c1, c2, c3;
    if (idx == 0)      { c0 = w0;  c1 = d21; c2 = d02; c3 = d10; }
    else if (idx == 1) { c0 = d21; c1 = w1;  c2 = s10; c3 = s02; }
    else if (idx == 2) { c0 = d02; c1 = s10; c2 = w2;  c3 = s21; }
    else               { c0 = d10; c1 = s02; c2 = s21; c3 = w3;  }

    float id = 0.5f * rsqrtf(best);     // best >= 1 (traces sum to 4)
    float q0 = c0*id, q1 = c1*id, q2 = c2*id, q3 = c3*id;

    float nrm2 = fmaxf(q1*q1 + q2*q2 + q3*q3, 1e-30f);
    float nrm  = nrm2 * rsqrtf(nrm2);
    float half = fast_atan2_pos(nrm, q0);
    float ang  = 2.0f * half;          // always >= 0

    float scale;
    if (ang < 1e-6f) {
        scale = FDIV(1.0f, 0.5f - ang*ang*(1.0f/48.0f));
    } else {
        float l2  = nrm2 + q0*q0;           // >= 0.25, never 0
        float len = l2 * rsqrtf(l2);
        scale = FDIV(ang * len, nrm);
    }
    o0 = q1*scale; o1 = q2*scale; o2 = q3*scale;
}

__global__ void __launch_bounds__(TPB, 3)
pose_kernel(const float* __restrict__ glb,   // (BT, 10, 6)
            const float* __restrict__ ori,   // (BT, 6, 6)
            float* __restrict__ out,         // (BT, 24, 3)
            int n)
{
    extern __shared__ float sg[];   // [TPB][60] unpadded

    int base = blockIdx.x * TPB;
    int samples = n - base; if (samples > TPB) samples = TPB;
    int t = threadIdx.x;

    const float* op = ori + (size_t)(base + t) * 36;
    bool active = (t < samples);

    // ---- prefetch O0 only (needed immediately after barrier) ----
    float4 oA0 = make_float4(0,0,0,0); float2 oA1 = make_float2(0,0);
    if (active) { oA0 = *(const float4*)(op + 0); oA1 = *(const float2*)(op + 4); }

    // ---- stage glb: straight float4 memcpy (coalesced, no remap) ----
    {
        const float4* __restrict__ src = (const float4*)(glb + (size_t)base * 60);
        float4* dst = (float4*)sg;
        int nf4 = samples * 15;           // 60/4 per sample
#pragma unroll 4
        for (int j = t; j < nf4; j += TPB) dst[j] = src[j];
    }
    __syncthreads();
    if (!active) return;

    const float* gp = sg + t * 60;
    float* po = out + (size_t)(base + t) * 72;

    float A[9], B[9], C[9], L[9], T[9];
    float a0,a1,a2, b0,b1,b2, c0,c1,c2, d0,d1,d2;

    // prefetch O1, O2 (consumed in group 2, ~600cyc of math away)
    float2 oB0 = *(const float2*)(op + 6);  float4 oB1 = *(const float4*)(op + 8);
    float4 oC0 = *(const float4*)(op + 12); float2 oC1 = *(const float2*)(op + 16);

    // ---- group 1: joints 0..3 (children of root: local == own R) ----
    r6d_core(oA0.x,oA0.y,oA0.z, oA0.w,oA1.x,oA1.y, L); mat_to_aa(L, a0,a1,a2); // j0 = root
    r6d_to_mat<true >(gp + 0, A);  mat_to_aa(A, b0,b1,b2);   // j1 = R1 (keep)
    r6d_to_mat<false>(gp + 6, B);  mat_to_aa(B, c0,c1,c2);   // j2 = R2 (keep)
    r6d_to_mat<true >(gp + 12, C); mat_to_aa(C, d0,d1,d2);   // j3 = R3 (keep)
    *(float4*)(po + 0) = make_float4(a0,a1,a2,b0);
    *(float4*)(po + 4) = make_float4(b1,b2,c0,c1);
    *(float4*)(po + 8) = make_float4(c2,d0,d1,d2);

    // ---- group 2: joints 4..7 (7 ignored) ----
    r6d_core(oB0.x,oB0.y,oB1.x, oB1.y,oB1.z,oB1.w, T);
    mat_tmul(A, T, L); mat_to_aa(L, a0,a1,a2);               // j4 = R1^T O1
    r6d_core(oC0.x,oC0.y,oC0.z, oC0.w,oC1.x,oC1.y, T);
    mat_tmul(B, T, L); mat_to_aa(L, b0,b1,b2);               // j5 = R2^T O2
    float R6[9];
    r6d_to_mat<false>(gp + 18, R6); mat_tmul(C, R6, L); mat_to_aa(L, c0,c1,c2); // j6 = R3^T R6
    *(float4*)(po + 12) = make_float4(a0,a1,a2,b0);
    *(float4*)(po + 16) = make_float4(b1,b2,c0,c1);
    *(float4*)(po + 20) = make_float4(c2,0.f,0.f,0.f);

    // prefetch O3 (consumed at end of group 4)
    float2 oD0 = *(const float2*)(op + 18); float4 oD1 = *(const float4*)(op + 20);

    // ---- group 3: joints 8..11 (8,10,11 ignored) ----
    float R9[9];
    r6d_to_mat<true >(gp + 24, R9); mat_tmul(R6, R9, L); mat_to_aa(L, b0,b1,b2); // j9
    *(float4*)(po + 24) = make_float4(0.f,0.f,0.f,b0);
    *(float4*)(po + 28) = make_float4(b1,b2,0.f,0.f);
    *(float4*)(po + 32) = make_float4(0.f,0.f,0.f,0.f);

    // prefetch O4, O5 (consumed in group 5)
    float4 oE0 = *(const float4*)(op + 24); float2 oE1 = *(const float2*)(op + 28);
    float2 oF0 = *(const float2*)(op + 30); float4 oF1 = *(const float4*)(op + 32);

    // ---- group 4: joints 12..15 ----
    r6d_to_mat<false>(gp + 30, A); mat_tmul(R9, A, L); mat_to_aa(L, a0,a1,a2); // j12 (A=R12)
    r6d_to_mat<true >(gp + 36, B); mat_tmul(R9, B, L); mat_to_aa(L, b0,b1,b2); // j13 (B=R13)
    r6d_to_mat<false>(gp + 42, C); mat_tmul(R9, C, L); mat_to_aa(L, c0,c1,c2); // j14 (C=R14)
    r6d_core(oD0.x,oD0.y,oD1.x, oD1.y,oD1.z,oD1.w, T);
    mat_tmul(A, T, L); mat_to_aa(L, d0,d1,d2);               // j15 = R12^T O3
    *(float4*)(po + 36) = make_float4(a0,a1,a2,b0);
    *(float4*)(po + 40) = make_float4(b1,b2,c0,c1);
    *(float4*)(po + 44) = make_float4(c2,d0,d1,d2);

    // ---- group 5: joints 16..19 ----
    r6d_to_mat<true >(gp + 48, A); mat_tmul(B, A, L); mat_to_aa(L, a0,a1,a2);  // j16 = R13^T R16
    r6d_to_mat<false>(gp + 54, B); mat_tmul(C, B, L); mat_to_aa(L, b0,b1,b2);  // j17 = R14^T R17
    r6d_core(oE0.x,oE0.y,oE0.z, oE0.w,oE1.x,oE1.y, T);
    mat_tmul(A, T, L); mat_to_aa(L, c0,c1,c2);               // j18 = R16^T O4
    r6d_core(oF0.x,oF0.y,oF1.x, oF1.y,oF1.z,oF1.w, T);
    mat_tmul(B, T, L); mat_to_aa(L, d0,d1,d2);               // j19 = R17^T O5
    *(float4*)(po + 48) = make_float4(a0,a1,a2,b0);
    *(float4*)(po + 52) = make_float4(b1,b2,c0,c1);
    *(float4*)(po + 56) = make_float4(c2,d0,d1,d2);

    // ---- group 6: joints 20..23 (all ignored) ----
    *(float4*)(po + 60) = make_float4(0.f,0.f,0.f,0.f);
    *(float4*)(po + 64) = make_float4(0.f,0.f,0.f,0.f);
    *(float4*)(po + 68) = make_float4(0.f,0.f,0.f,0.f);
}

extern "C" void kernel_launch(void* const* d_in, const int* in_sizes, int n_in,
                              void* d_out, int out_size) {
    const float* glb;
    const float* ori;
    if (in_sizes[0] >= in_sizes[1]) {
        glb = (const float*)d_in[0];
        ori = (const float*)d_in[1];
    } else {
        glb = (const float*)d_in[1];
        ori = (const float*)d_in[0];
    }
    int n = out_size / 72;

    static bool attr_set = false;
    if (!attr_set) {
        cudaFuncSetAttribute(pose_kernel,
                             cudaFuncAttributeMaxDynamicSharedMemorySize,
                             SMEM_BYTES);
        attr_set = true;
    }

    const int blocks = (n + TPB - 1) / TPB;
    pose_kernel<<<blocks, TPB, SMEM_BYTES>>>(glb, ori, (float*)d_out, n);
}

// round 13
// speedup vs baseline: 1.2515x; 1.1066x over previous
#include <cuda_runtime.h>
#include <math.h>

// ---------------------------------------------------------------------------
// HumanPoseModule, fully joint-parallel.
// Identity: local_c = R_parent^T @ R_own over RAW per-joint 6d->matrix
// conversions (root cancels; orthonormal) => no FK chain. One lane per
// (sample, joint): 16 joint-slots per sample, 2 samples per warp.
// Inputs staged in smem (padded stride-104 records); outputs assembled in a
// per-warp smem buffer (zeros for ignored joints) then stored coalesced.
// ---------------------------------------------------------------------------

#define FDIV(a,b) __fdividef((a),(b))

constexpr int TPB  = 256;          // 8 warps; 16 samples/block
constexpr int SPB  = 16;           // samples per block
constexpr int REC  = 104;          // padded record stride (floats); 104%32=8
// record layout: glb[0..59], ori at [60..95]

// slot -> (parent_off | own_off<<8 | out_float_off<<16); parent 255 = none.
// glb order: R1,R2,R3,R6,R9,R12,R13,R14,R16,R17 at float offsets 0,6,...,54
// ori order: O0,O1,O2,O3,O4,O5 at 60,66,72,78,84,90
__constant__ int kSlot[16] = {
    (255) | ( 60 << 8) | ( 0 << 16),   // j0  = O0 (root)
    (255) | (  0 << 8) | ( 3 << 16),   // j1  = R1
    (255) | (  6 << 8) | ( 6 << 16),   // j2  = R2
    (255) | ( 12 << 8) | ( 9 << 16),   // j3  = R3
    (  0) | ( 66 << 8) | (12 << 16),   // j4  = R1^T O1
    (  6) | ( 72 << 8) | (15 << 16),   // j5  = R2^T O2
    ( 12) | ( 18 << 8) | (18 << 16),   // j6  = R3^T R6
    ( 18) | ( 24 << 8) | (27 << 16),   // j9  = R6^T R9
    ( 24) | ( 30 << 8) | (36 << 16),   // j12 = R9^T R12
    ( 24) | ( 36 << 8) | (39 << 16),   // j13 = R9^T R13
    ( 24) | ( 42 << 8) | (42 << 16),   // j14 = R9^T R14
    ( 30) | ( 78 << 8) | (45 << 16),   // j15 = R12^T O3
    ( 36) | ( 48 << 8) | (48 << 16),   // j16 = R13^T R16
    ( 42) | ( 54 << 8) | (51 << 16),   // j17 = R14^T R17
    ( 48) | ( 84 << 8) | (54 << 16),   // j18 = R16^T O4
    ( 54) | ( 90 << 8) | (57 << 16),   // j19 = R17^T O5
};

// Octant-reduced atan2 for y >= 0 (result in [0, pi]); deg-11 minimax, ~2e-8.
__device__ __forceinline__ float fast_atan2_pos(float y, float x) {
    float ax = fabsf(x);
    float mn = fminf(y, ax);
    float mx = fmaxf(y, ax);
    float t  = FDIV(mn, mx);
    float t2 = t * t;
    float p = -0.0117212f;
    p = fmaf(p, t2,  0.05265332f);
    p = fmaf(p, t2, -0.11643287f);
    p = fmaf(p, t2,  0.19354346f);
    p = fmaf(p, t2, -0.33262347f);
    p = fmaf(p, t2,  0.99997726f);
    p = p * t;
    float r = (y > ax) ? (1.57079632679f - p) : p;
    if (x < 0.0f) r = 3.14159265359f - r;
    return r;
}

// 6 floats (from smem, float2-aligned: all offsets even) -> rotation matrix
__device__ __forceinline__ void r6d_to_mat(const float* __restrict__ p, float R[9]) {
    float2 v0 = *(const float2*)(p + 0);
    float2 v1 = *(const float2*)(p + 2);
    float2 v2 = *(const float2*)(p + 4);
    float a1x = v0.x, a1y = v0.y, a1z = v1.x;
    float a2x = v1.y, a2y = v2.x, a2z = v2.y;

    float in1 = rsqrtf(a1x*a1x + a1y*a1y + a1z*a1z);
    float b1x = a1x*in1, b1y = a1y*in1, b1z = a1z*in1;

    float dt = b1x*a2x + b1y*a2y + b1z*a2z;
    float b2x = a2x - dt*b1x, b2y = a2y - dt*b1y, b2z = a2z - dt*b1z;
    float in2 = rsqrtf(b2x*b2x + b2y*b2y + b2z*b2z);
    b2x *= in2; b2y *= in2; b2z *= in2;

    R[0]=b1x; R[1]=b1y; R[2]=b1z;
    R[3]=b2x; R[4]=b2y; R[5]=b2z;
    R[6] = b1y*b2z - b1z*b2y;
    R[7] = b1z*b2x - b1x*b2z;
    R[8] = b1x*b2y - b1y*b2x;
}

// C = A^T @ B
__device__ __forceinline__ void mat_tmul(const float A[9], const float B[9], float C[9]) {
#pragma unroll
    for (int i = 0; i < 3; i++)
#pragma unroll
        for (int j = 0; j < 3; j++)
            C[3*i+j] = A[0+i]*B[0+j] + A[3+i]*B[3+j] + A[6+i]*B[6+j];
}

// matrix -> axis-angle (reference-equivalent; see prior-round derivations)
__device__ __forceinline__ void mat_to_aa(const float m[9],
                                          float& o0, float& o1, float& o2) {
    float m00=m[0], m01=m[1], m02=m[2];
    float m10=m[3], m11=m[4], m12=m[5];
    float m20=m[6], m21=m[7], m22=m[8];

    float w0 = fmaxf(1.0f + m00 + m11 + m22, 0.0f);
    float w1 = fmaxf(1.0f + m00 - m11 - m22, 0.0f);
    float w2 = fmaxf(1.0f - m00 + m11 - m22, 0.0f);
    float w3 = fmaxf(1.0f - m00 - m11 + m22, 0.0f);

    int idx = 0; float best = w0;
    if (w1 > best) { best = w1; idx = 1; }
    if (w2 > best) { best = w2; idx = 2; }
    if (w3 > best) { best = w3; idx = 3; }

    float d21 = m21 - m12, d02 = m02 - m20, d10 = m10 - m01;
    float s10 = m10 + m01, s02 = m02 + m20, s21 = m21 + m12;

    float c0, c1, c2, c3;
    if (idx == 0)      { c0 = w0;  c1 = d21; c2 = d02; c3 = d10; }
    else if (idx == 1) { c0 = d21; c1 = w1;  c2 = s10; c3 = s02; }
    else if (idx == 2) { c0 = d02; c1 = s10; c2 = w2;  c3 = s21; }
    else               { c0 = d10; c1 = s02; c2 = s21; c3 = w3;  }

    float id = 0.5f * rsqrtf(best);     // best >= 1 (traces sum to 4)
    float q0 = c0*id, q1 = c1*id, q2 = c2*id, q3 = c3*id;

    float nrm2 = fmaxf(q1*q1 + q2*q2 + q3*q3, 1e-30f);
    float nrm  = nrm2 * rsqrtf(nrm2);
    float half = fast_atan2_pos(nrm, q0);
    float ang  = 2.0f * half;          // >= 0 always

    float scale;
    if (ang < 1e-6f) {
        scale = FDIV(1.0f, 0.5f - ang*ang*(1.0f/48.0f));
    } else {
        float l2  = nrm2 + q0*q0;           // >= 0.25, never 0
        float len = l2 * rsqrtf(l2);
        scale = FDIV(ang * len, nrm);
    }
    o0 = q1*scale; o1 = q2*scale; o2 = q3*scale;
}

__global__ void __launch_bounds__(TPB, 8)
pose_kernel(const float* __restrict__ glb,   // (BT, 10, 6)
            const float* __restrict__ ori,   // (BT, 6, 6)
            float* __restrict__ out,         // (BT, 24, 3)
            int n)
{
    __shared__ float sin_[SPB * REC];        // staged inputs: 6656 B
    __shared__ float sout[SPB * 72];         // assembled outputs: 4608 B

    int base = blockIdx.x * SPB;
    int samples = n - base; if (samples > SPB) samples = SPB;
    int t = threadIdx.x;

    // ---- stage glb: samples*60 floats as float4 (60,104 both %4==0) ----
    {
        const float4* __restrict__ src = (const float4*)(glb + (size_t)base * 60);
        int nf4 = samples * 15;
        for (int j = t; j < nf4; j += TPB) {
            float4 v = src[j];
            int f = 4*j; int s = f / 60; int k = f - s*60;
            *(float4*)(sin_ + s*REC + k) = v;
        }
    }
    // ---- stage ori: samples*36 floats ----
    {
        const float4* __restrict__ src = (const float4*)(ori + (size_t)base * 36);
        int nf4 = samples * 9;
        for (int j = t; j < nf4; j += TPB) {
            float4 v = src[j];
            int f = 4*j; int s = f / 36; int k = f - s*36;
            *(float4*)(sin_ + s*REC + 60 + k) = v;
        }
    }
    // ---- zero the out buffer (covers ignored joints) ----
    {
        float4* ov = (float4*)sout;
        for (int j = t; j < SPB*72/4; j += TPB)
            ov[j] = make_float4(0.f, 0.f, 0.f, 0.f);
    }
    __syncthreads();

    int lane = t & 31;
    int warp = t >> 5;
    int s_local = (warp << 1) | (lane >> 4);   // sample index in block
    int slot = lane & 15;

    if (s_local < samples) {
        int e = kSlot[slot];
        int par = e & 255;
        int own = (e >> 8) & 255;
        int oout = (e >> 16) & 255;

        const float* rec = sin_ + s_local * REC;

        float OWN[9], L[9];
        r6d_to_mat(rec + own, OWN);
        if (par != 255) {
            float P[9];
            r6d_to_mat(rec + par, P);
            mat_tmul(P, OWN, L);
        } else {
#pragma unroll
            for (int k = 0; k < 9; k++) L[k] = OWN[k];
        }

        float a0, a1, a2;
        mat_to_aa(L, a0, a1, a2);

        float* po = sout + s_local * 72 + oout;
        po[0] = a0; po[1] = a1; po[2] = a2;
    }
    __syncwarp();

    // ---- per-warp coalesced store: 2 samples x 72 floats = 36 float4 ----
    {
        int sw = warp << 1;                       // first sample of this warp
        int valid = samples - sw;                 // 0..2
        if (valid > 0) {
            if (valid > 2) valid = 2;
            int nf4 = valid * 18;
            const float4* sv = (const float4*)(sout + sw * 72);
            float4* dv = (float4*)(out + (size_t)(base + sw) * 72);
            for (int j = lane; j < nf4; j += 32)
                dv[j] = sv[j];
        }
    }
}

extern "C" void kernel_launch(void* const* d_in, const int* in_sizes, int n_in,
                              void* d_out, int out_size) {
    const float* glb;
    const float* ori;
    if (in_sizes[0] >= in_sizes[1]) {
        glb = (const float*)d_in[0];
        ori = (const float*)d_in[1];
    } else {
        glb = (const float*)d_in[1];
        ori = (const float*)d_in[0];
    }
    int n = out_size / 72;

    const int blocks = (n + SPB - 1) / SPB;
    pose_kernel<<<blocks, TPB>>>(glb, ori, (float*)d_out, n);
}

// round 14
// speedup vs baseline: 1.6099x; 1.2864x over previous
#include <cuda_runtime.h>
#include <math.h>

// ---------------------------------------------------------------------------
// HumanPoseModule, joint-parallel with warp-level matrix dedup.
// local_c = R_parent^T @ R_own over RAW 6d->matrix conversions (root cancels).
// One lane per (sample, joint-slot): 16 slots/sample, 2 samples/warp.
// Phase 1: each lane converts its UNIQUE record (bijection), STS matrix.
// Phase 2: lane LDS parent matrix (slot 16 = identity for root children,
// exact FMA pass-through), tmul, axis-angle, STS to out buffer, coalesced STG.
// No div/mod anywhere; no __syncthreads (warps self-contained).
// ---------------------------------------------------------------------------

#define FDIV(a,b) __fdividef((a),(b))

constexpr int TPB = 256;            // 8 warps, 16 samples per block
constexpr int SPB = 16;
constexpr int MS  = 12;             // matrix slot stride (floats)
constexpr int SSTRIDE = 17 * MS;    // per-sample: 16 mats + identity = 204

// slot -> own_off(7) | is_ori<<7 | parent_slot<<8 | out_float_off<<16
__constant__ int kSlot[16] = {
    (  0 | 128) | (16 << 8) | ( 0 << 16),   // j0  = O0 (root)
    (  0      ) | (16 << 8) | ( 3 << 16),   // j1  = R1
    (  6      ) | (16 << 8) | ( 6 << 16),   // j2  = R2
    ( 12      ) | (16 << 8) | ( 9 << 16),   // j3  = R3
    (  6 | 128) | ( 1 << 8) | (12 << 16),   // j4  = R1^T O1
    ( 12 | 128) | ( 2 << 8) | (15 << 16),   // j5  = R2^T O2
    ( 18      ) | ( 3 << 8) | (18 << 16),   // j6  = R3^T R6
    ( 24      ) | ( 6 << 8) | (27 << 16),   // j9  = R6^T R9
    ( 30      ) | ( 7 << 8) | (36 << 16),   // j12 = R9^T R12
    ( 36      ) | ( 7 << 8) | (39 << 16),   // j13 = R9^T R13
    ( 42      ) | ( 7 << 8) | (42 << 16),   // j14 = R9^T R14
    ( 18 | 128) | ( 8 << 8) | (45 << 16),   // j15 = R12^T O3
    ( 48      ) | ( 9 << 8) | (48 << 16),   // j16 = R13^T R16
    ( 54      ) | (10 << 8) | (51 << 16),   // j17 = R14^T R17
    ( 24 | 128) | (12 << 8) | (54 << 16),   // j18 = R16^T O4
    ( 30 | 128) | (13 << 8) | (57 << 16),   // j19 = R17^T O5
};

// Octant-reduced atan2 for y >= 0 (result in [0, pi]); deg-11 minimax, ~2e-8.
__device__ __forceinline__ float fast_atan2_pos(float y, float x) {
    float ax = fabsf(x);
    float mn = fminf(y, ax);
    float mx = fmaxf(y, ax);
    float t  = FDIV(mn, mx);
    float t2 = t * t;
    float p = -0.0117212f;
    p = fmaf(p, t2,  0.05265332f);
    p = fmaf(p, t2, -0.11643287f);
    p = fmaf(p, t2,  0.19354346f);
    p = fmaf(p, t2, -0.33262347f);
    p = fmaf(p, t2,  0.99997726f);
    p = p * t;
    float r = (y > ax) ? (1.57079632679f - p) : p;
    if (x < 0.0f) r = 3.14159265359f - r;
    return r;
}

// matrix -> axis-angle (reference-equivalent; see prior-round derivations)
__device__ __forceinline__ void mat_to_aa(const float m[9],
                                          float& o0, float& o1, float& o2) {
    float m00=m[0], m01=m[1], m02=m[2];
    float m10=m[3], m11=m[4], m12=m[5];
    float m20=m[6], m21=m[7], m22=m[8];

    float w0 = fmaxf(1.0f + m00 + m11 + m22, 0.0f);
    float w1 = fmaxf(1.0f + m00 - m11 - m22, 0.0f);
    float w2 = fmaxf(1.0f - m00 + m11 - m22, 0.0f);
    float w3 = fmaxf(1.0f - m00 - m11 + m22, 0.0f);

    int idx = 0; float best = w0;
    if (w1 > best) { best = w1; idx = 1; }
    if (w2 > best) { best = w2; idx = 2; }
    if (w3 > best) { best = w3; idx = 3; }

    float d21 = m21 - m12, d02 = m02 - m20, d10 = m10 - m01;
    float s10 = m10 + m01, s02 = m02 + m20, s21 = m21 + m12;

    float c0, c1, c2, c3;
    if (idx == 0)      { c0 = w0;  c1 = d21; c2 = d02; c3 = d10; }
    else if (idx == 1) { c0 = d21; c1 = w1;  c2 = s10; c3 = s02; }
    else if (idx == 2) { c0 = d02; c1 = s10; c2 = w2;  c3 = s21; }
    else               { c0 = d10; c1 = s02; c2 = s21; c3 = w3;  }

    float id = 0.5f * rsqrtf(best);     // best >= 1 (traces sum to 4)
    float q0 = c0*id, q1 = c1*id, q2 = c2*id, q3 = c3*id;

    float nrm2 = fmaxf(q1*q1 + q2*q2 + q3*q3, 1e-30f);
    float nrm  = nrm2 * rsqrtf(nrm2);
    float half = fast_atan2_pos(nrm, q0);
    float ang  = 2.0f * half;          // >= 0 always

    float scale;
    if (ang < 1e-6f) {
        scale = FDIV(1.0f, 0.5f - ang*ang*(1.0f/48.0f));
    } else {
        float l2  = nrm2 + q0*q0;           // >= 0.25, never 0
        float len = l2 * rsqrtf(l2);
        scale = FDIV(ang * len, nrm);
    }
    o0 = q1*scale; o1 = q2*scale; o2 = q3*scale;
}

__global__ void __launch_bounds__(TPB, 6)
pose_kernel(const float* __restrict__ glb,   // (BT, 10, 6)
            const float* __restrict__ ori,   // (BT, 6, 6)
            float* __restrict__ out,         // (BT, 24, 3)
            int n)
{
    __shared__ float smat[SPB * SSTRIDE];    // 13,056 B
    __shared__ float sout[SPB * 72];         //  4,608 B

    int t    = threadIdx.x;
    int lane = t & 31;
    int warp = t >> 5;
    int s_local  = (warp << 1) | (lane >> 4);            // 0..15
    int slot     = lane & 15;
    int s_global = blockIdx.x * SPB + s_local;
    bool active  = (s_global < n);

    // ---- zero this warp's out region (36 float4 per warp) ----
    {
        float4* z = (float4*)(sout + (warp << 1) * 72);
        z[lane] = make_float4(0.f, 0.f, 0.f, 0.f);
        if (lane < 4) z[lane + 32] = make_float4(0.f, 0.f, 0.f, 0.f);
    }

    int e   = kSlot[slot];
    int par = (e >> 8) & 31;
    int oo  = (e >> 16) & 255;

    float OWN[9];
    if (active) {
        // ---- phase 1: load own 6d record (unique per lane), convert ----
        int off = e & 127;
        const float* src = (e & 128) ? (ori + (size_t)s_global * 36 + off)
                                     : (glb + (size_t)s_global * 60 + off);
        float2 v0 = __ldg((const float2*)(src + 0));
        float2 v1 = __ldg((const float2*)(src + 2));
        float2 v2 = __ldg((const float2*)(src + 4));
        float a1x = v0.x, a1y = v0.y, a1z = v1.x;
        float a2x = v1.y, a2y = v2.x, a2z = v2.y;

        float in1 = rsqrtf(a1x*a1x + a1y*a1y + a1z*a1z);
        float b1x = a1x*in1, b1y = a1y*in1, b1z = a1z*in1;
        float dt = b1x*a2x + b1y*a2y + b1z*a2z;
        float b2x = a2x - dt*b1x, b2y = a2y - dt*b1y, b2z = a2z - dt*b1z;
        float in2 = rsqrtf(b2x*b2x + b2y*b2y + b2z*b2z);
        b2x *= in2; b2y *= in2; b2z *= in2;

        OWN[0]=b1x; OWN[1]=b1y; OWN[2]=b1z;
        OWN[3]=b2x; OWN[4]=b2y; OWN[5]=b2z;
        OWN[6] = b1y*b2z - b1z*b2y;
        OWN[7] = b1z*b2x - b1x*b2z;
        OWN[8] = b1x*b2y - b1y*b2x;

        // ---- store matrix to smem (stride 12: conflict-free STS.128) ----
        float* mp = smat + (s_local * 17 + slot) * MS;
        *(float4*)(mp + 0) = make_float4(OWN[0], OWN[1], OWN[2], OWN[3]);
        *(float4*)(mp + 4) = make_float4(OWN[4], OWN[5], OWN[6], OWN[7]);
        *(float4*)(mp + 8) = make_float4(OWN[8], 0.f, 0.f, 0.f);

        // slot-0 lane also writes the per-sample identity matrix (slot 16)
        if (slot == 0) {
            float* ip = smat + (s_local * 17 + 16) * MS;
            *(float4*)(ip + 0) = make_float4(1.f, 0.f, 0.f, 0.f);
            *(float4*)(ip + 4) = make_float4(1.f, 0.f, 0.f, 0.f);
            *(float4*)(ip + 8) = make_float4(1.f, 0.f, 0.f, 0.f);
        }
    }
    __syncwarp();

    if (active) {
        // ---- phase 2: read parent matrix, L = P^T OWN, axis-angle ----
        const float* pp = smat + (s_local * 17 + par) * MS;
        float4 p0 = *(const float4*)(pp + 0);
        float4 p1 = *(const float4*)(pp + 4);
        float  p8 = pp[8];
        float P[9] = {p0.x, p0.y, p0.z, p0.w, p1.x, p1.y, p1.z, p1.w, p8};

        float L[9];
#pragma unroll
        for (int i = 0; i < 3; i++)
#pragma unroll
            for (int j = 0; j < 3; j++)
                L[3*i+j] = P[0+i]*OWN[0+j] + P[3+i]*OWN[3+j] + P[6+i]*OWN[6+j];

        float a0, a1, a2;
        mat_to_aa(L, a0, a1, a2);

        float* po = sout + s_local * 72 + oo;
        po[0] = a0; po[1] = a1; po[2] = a2;
    }
    __syncwarp();

    // ---- coalesced store: warp's 2 samples = 36 float4 ----
    {
        int sw = (blockIdx.x * SPB) + (warp << 1);
        int valid = n - sw; if (valid > 2) valid = 2;
        if (valid > 0) {
            int nf4 = valid * 18;
            const float4* sv = (const float4*)(sout + (warp << 1) * 72);
            float4* dv = (float4*)(out + (size_t)sw * 72);
            if (lane < nf4) dv[lane] = sv[lane];
            if (lane + 32 < nf4) dv[lane + 32] = sv[lane + 32];
        }
    }
}

extern "C" void kernel_launch(void* const* d_in, const int* in_sizes, int n_in,
                              void* d_out, int out_size) {
    const float* glb;
    const float* ori;
    if (in_sizes[0] >= in_sizes[1]) {
        glb = (const float*)d_in[0];
        ori = (const float*)d_in[1];
    } else {
        glb = (const float*)d_in[1];
        ori = (const float*)d_in[0];
    }
    int n = out_size / 72;

    const int blocks = (n + SPB - 1) / SPB;
    pose_kernel<<<blocks, TPB>>>(glb, ori, (float*)d_out, n);
}

// round 15
// speedup vs baseline: 1.7060x; 1.0597x over previous
#include <cuda_runtime.h>
#include <math.h>

// ---------------------------------------------------------------------------
// HumanPoseModule, joint-parallel with SHUFFLE-based parent-matrix sharing.
// local_c = R_parent^T @ R_own over RAW 6d->matrix conversions (root cancels).
// One lane per (sample, joint-slot): 16 slots/sample, 2 samples/warp.
// Each lane converts its UNIQUE record; parent matrix obtained via 9 warp
// shuffles from the parent slot's lane (identity via FSEL for root children:
// exact FMA pass-through). Outputs assembled in a tiny per-warp smem buffer
// (zeros for ignored joints) then stored coalesced. Fully convergent.
// ---------------------------------------------------------------------------

#define FDIV(a,b) __fdividef((a),(b))

constexpr int TPB = 256;            // 8 warps, 16 samples per block
constexpr int SPB = 16;

// slot -> own_off(7) | is_ori<<7 | parent_slot<<8 | is_root<<13 | out_off<<16
// glb records: R1,R2,R3,R6,R9,R12,R13,R14,R16,R17 at 0,6,...,54
// ori records: O0..O5 at 0,6,12,18,24,30
__constant__ int kSlot[16] = {
    (  0 | 128) | ( 0 << 8) | (1 << 13) | ( 0 << 16),   // j0  = O0 (root)
    (  0      ) | ( 0 << 8) | (1 << 13) | ( 3 << 16),   // j1  = R1
    (  6      ) | ( 0 << 8) | (1 << 13) | ( 6 << 16),   // j2  = R2
    ( 12      ) | ( 0 << 8) | (1 << 13) | ( 9 << 16),   // j3  = R3
    (  6 | 128) | ( 1 << 8) | (0 << 13) | (12 << 16),   // j4  = R1^T O1
    ( 12 | 128) | ( 2 << 8) | (0 << 13) | (15 << 16),   // j5  = R2^T O2
    ( 18      ) | ( 3 << 8) | (0 << 13) | (18 << 16),   // j6  = R3^T R6
    ( 24      ) | ( 6 << 8) | (0 << 13) | (27 << 16),   // j9  = R6^T R9
    ( 30      ) | ( 7 << 8) | (0 << 13) | (36 << 16),   // j12 = R9^T R12
    ( 36      ) | ( 7 << 8) | (0 << 13) | (39 << 16),   // j13 = R9^T R13
    ( 42      ) | ( 7 << 8) | (0 << 13) | (42 << 16),   // j14 = R9^T R14
    ( 18 | 128) | ( 8 << 8) | (0 << 13) | (45 << 16),   // j15 = R12^T O3
    ( 48      ) | ( 9 << 8) | (0 << 13) | (48 << 16),   // j16 = R13^T R16
    ( 54      ) | (10 << 8) | (0 << 13) | (51 << 16),   // j17 = R14^T R17
    ( 24 | 128) | (12 << 8) | (0 << 13) | (54 << 16),   // j18 = R16^T O4
    ( 30 | 128) | (13 << 8) | (0 << 13) | (57 << 16),   // j19 = R17^T O5
};

// Octant-reduced atan2 for y >= 0 (result in [0, pi]); deg-11 minimax, ~2e-8.
__device__ __forceinline__ float fast_atan2_pos(float y, float x) {
    float ax = fabsf(x);
    float mn = fminf(y, ax);
    float mx = fmaxf(y, ax);
    float t  = FDIV(mn, mx);
    float t2 = t * t;
    float p = -0.0117212f;
    p = fmaf(p, t2,  0.05265332f);
    p = fmaf(p, t2, -0.11643287f);
    p = fmaf(p, t2,  0.19354346f);
    p = fmaf(p, t2, -0.33262347f);
    p = fmaf(p, t2,  0.99997726f);
    p = p * t;
    float r = (y > ax) ? (1.57079632679f - p) : p;
    if (x < 0.0f) r = 3.14159265359f - r;
    return r;
}

// matrix -> axis-angle (reference-equivalent; see prior-round derivations)
__device__ __forceinline__ void mat_to_aa(const float m[9],
                                          float& o0, float& o1, float& o2) {
    float m00=m[0], m01=m[1], m02=m[2];
    float m10=m[3], m11=m[4], m12=m[5];
    float m20=m[6], m21=m[7], m22=m[8];

    float w0 = fmaxf(1.0f + m00 + m11 + m22, 0.0f);
    float w1 = fmaxf(1.0f + m00 - m11 - m22, 0.0f);
    float w2 = fmaxf(1.0f - m00 + m11 - m22, 0.0f);
    float w3 = fmaxf(1.0f - m00 - m11 + m22, 0.0f);

    int idx = 0; float best = w0;
    if (w1 > best) { best = w1; idx = 1; }
    if (w2 > best) { best = w2; idx = 2; }
    if (w3 > best) { best = w3; idx = 3; }

    float d21 = m21 - m12, d02 = m02 - m20, d10 = m10 - m01;
    float s10 = m10 + m01, s02 = m02 + m20, s21 = m21 + m12;

    float c0, c1, c2, c3;
    if (idx == 0)      { c0 = w0;  c1 = d21; c2 = d02; c3 = d10; }
    else if (idx == 1) { c0 = d21; c1 = w1;  c2 = s10; c3 = s02; }
    else if (idx == 2) { c0 = d02; c1 = s10; c2 = w2;  c3 = s21; }
    else               { c0 = d10; c1 = s02; c2 = s21; c3 = w3;  }

    float id = 0.5f * rsqrtf(best);     // best >= 1 (traces sum to 4)
    float q0 = c0*id, q1 = c1*id, q2 = c2*id, q3 = c3*id;

    float nrm2 = fmaxf(q1*q1 + q2*q2 + q3*q3, 1e-30f);
    float nrm  = nrm2 * rsqrtf(nrm2);
    float half = fast_atan2_pos(nrm, q0);
    float ang  = 2.0f * half;          // >= 0 always

    float scale;
    if (ang < 1e-6f) {
        scale = FDIV(1.0f, 0.5f - ang*ang*(1.0f/48.0f));
    } else {
        float l2  = nrm2 + q0*q0;           // >= 0.25, never 0
        float len = l2 * rsqrtf(l2);
        scale = FDIV(ang * len, nrm);
    }
    o0 = q1*scale; o1 = q2*scale; o2 = q3*scale;
}

__global__ void __launch_bounds__(TPB, 8)
pose_kernel(const float* __restrict__ glb,   // (BT, 10, 6)
            const float* __restrict__ ori,   // (BT, 6, 6)
            float* __restrict__ out,         // (BT, 24, 3)
            int n)
{
    __shared__ float sout[SPB * 72];         // 4,608 B

    int t    = threadIdx.x;
    int lane = t & 31;
    int warp = t >> 5;
    int s_local  = (warp << 1) | (lane >> 4);            // 0..15
    int slot     = lane & 15;
    int s_global = blockIdx.x * SPB + s_local;
    bool active  = (s_global < n);
    int s_clamp  = active ? s_global : (n - 1);          // convergent loads

    // ---- zero this warp's out region (36 float4 per warp) ----
    {
        float4* z = (float4*)(sout + (warp << 1) * 72);
        z[lane] = make_float4(0.f, 0.f, 0.f, 0.f);
        if (lane < 4) z[lane + 32] = make_float4(0.f, 0.f, 0.f, 0.f);
    }

    int e      = kSlot[slot];
    int parSrc = (lane & 16) | ((e >> 8) & 15);
    bool isRoot = (e & (1 << 13)) != 0;
    int oo     = (e >> 16) & 255;

    // ---- convert own 6d record (unique per lane) ----
    float OWN[9];
    {
        int off = e & 127;
        const float* src = (e & 128) ? (ori + (size_t)s_clamp * 36 + off)
                                     : (glb + (size_t)s_clamp * 60 + off);
        float2 v0 = __ldg((const float2*)(src + 0));
        float2 v1 = __ldg((const float2*)(src + 2));
        float2 v2 = __ldg((const float2*)(src + 4));
        float a1x = v0.x, a1y = v0.y, a1z = v1.x;
        float a2x = v1.y, a2y = v2.x, a2z = v2.y;

        float in1 = rsqrtf(a1x*a1x + a1y*a1y + a1z*a1z);
        float b1x = a1x*in1, b1y = a1y*in1, b1z = a1z*in1;
        float dt = b1x*a2x + b1y*a2y + b1z*a2z;
        float b2x = a2x - dt*b1x, b2y = a2y - dt*b1y, b2z = a2z - dt*b1z;
        float in2 = rsqrtf(b2x*b2x + b2y*b2y + b2z*b2z);
        b2x *= in2; b2y *= in2; b2z *= in2;

        OWN[0]=b1x; OWN[1]=b1y; OWN[2]=b1z;
        OWN[3]=b2x; OWN[4]=b2y; OWN[5]=b2z;
        OWN[6] = b1y*b2z - b1z*b2y;
        OWN[7] = b1z*b2x - b1x*b2z;
        OWN[8] = b1x*b2y - b1y*b2x;
    }

    // ---- parent matrix via warp shuffles (identity for root children) ----
    float P[9];
#pragma unroll
    for (int j = 0; j < 9; j++)
        P[j] = __shfl_sync(0xffffffffu, OWN[j], parSrc);
    // identity select: diag -> 1, off-diag -> 0 when root child
    if (isRoot) {
        P[0] = 1.f; P[1] = 0.f; P[2] = 0.f;
        P[3] = 0.f; P[4] = 1.f; P[5] = 0.f;
        P[6] = 0.f; P[7] = 0.f; P[8] = 1.f;
    }

    // ---- L = P^T @ OWN, then axis-angle ----
    float L[9];
#pragma unroll
    for (int i = 0; i < 3; i++)
#pragma unroll
        for (int j = 0; j < 3; j++)
            L[3*i+j] = P[0+i]*OWN[0+j] + P[3+i]*OWN[3+j] + P[6+i]*OWN[6+j];

    float a0, a1, a2;
    mat_to_aa(L, a0, a1, a2);

    __syncwarp();                          // zero-fill visible before scatter
    if (active) {
        float* po = sout + s_local * 72 + oo;
        po[0] = a0; po[1] = a1; po[2] = a2;
    }
    __syncwarp();

    // ---- coalesced store: warp's 2 samples = 36 float4 ----
    {
        int sw = (blockIdx.x * SPB) + (warp << 1);
        int valid = n - sw; if (valid > 2) valid = 2;
        if (valid > 0) {
            int nf4 = valid * 18;
            const float4* sv = (const float4*)(sout + (warp << 1) * 72);
            float4* dv = (float4*)(out + (size_t)sw * 72);
            if (lane < nf4) dv[lane] = sv[lane];
            if (lane + 32 < nf4) dv[lane + 32] = sv[lane + 32];
        }
    }
}

extern "C" void kernel_launch(void* const* d_in, const int* in_sizes, int n_in,
                              void* d_out, int out_size) {
    const float* glb;
    const float* ori;
    if (in_sizes[0] >= in_sizes[1]) {
        glb = (const float*)d_in[0];
        ori = (const float*)d_in[1];
    } else {
        glb = (const float*)d_in[1];
        ori = (const float*)d_in[0];
    }
    int n = out_size / 72;

    const int blocks = (n + SPB - 1) / SPB;
    pose_kernel<<<blocks, TPB>>>(glb, ori, (float*)d_out, n);
}